// round 1
// baseline (speedup 1.0000x reference)
#include <cuda_runtime.h>
#include <cuda_bf16.h>
#include <math.h>

// Problem constants (fixed shapes per reference)
#define MAXN   100000
#define FDIM   44
#define F2DIM  88
#define FEATD  1019
#define MAXG   1024

// Scratch (allocation-free rule: static __device__ globals)
__device__ __align__(256) float g_bufA[MAXN * F2DIM];   // 35.2 MB
__device__ __align__(256) float g_bufB[MAXN * F2DIM];   // 35.2 MB
__device__ __align__(256) float g_dinv[MAXN];
__device__ __align__(256) float g_pool[MAXG * FDIM];

// ---------------------------------------------------------------- degree/norm
__global__ void k_set_deg(float* deg, int n) {
    int i = blockIdx.x * blockDim.x + threadIdx.x;
    if (i < n) deg[i] = 1.0f;              // self-loop
}
__global__ void k_count_deg(const int* __restrict__ dst, float* deg, int E) {
    int e = blockIdx.x * blockDim.x + threadIdx.x;
    if (e < E) atomicAdd(&deg[dst[e]], 1.0f);
}
__global__ void k_dinv(float* deg, int n) {
    int i = blockIdx.x * blockDim.x + threadIdx.x;
    if (i < n) deg[i] = rsqrtf(deg[i]);    // in-place: deg -> dinv
}

// ---------------------------------------------------------------- t = act(h) @ W
// One thread computes a float4 of the output row. Kin, Kout divisible by 4.
__global__ void k_mm(const float* __restrict__ h, const float* __restrict__ W,
                     float* __restrict__ t, int n, int Kin, int Kout4, int relu) {
    int item = blockIdx.x * blockDim.x + threadIdx.x;
    int total = n * Kout4;
    if (item >= total) return;
    int row = item / Kout4;
    int c4  = item - row * Kout4;
    const float*  hrow = h + row * Kin;
    const float4* Wv   = (const float4*)W;
    float4 acc = make_float4(0.f, 0.f, 0.f, 0.f);
    for (int k = 0; k < Kin; k += 4) {
        float4 hv = *(const float4*)(hrow + k);
        if (relu) {
            hv.x = fmaxf(hv.x, 0.f); hv.y = fmaxf(hv.y, 0.f);
            hv.z = fmaxf(hv.z, 0.f); hv.w = fmaxf(hv.w, 0.f);
        }
        float4 w0 = Wv[(k + 0) * Kout4 + c4];
        acc.x = fmaf(hv.x, w0.x, acc.x); acc.y = fmaf(hv.x, w0.y, acc.y);
        acc.z = fmaf(hv.x, w0.z, acc.z); acc.w = fmaf(hv.x, w0.w, acc.w);
        float4 w1 = Wv[(k + 1) * Kout4 + c4];
        acc.x = fmaf(hv.y, w1.x, acc.x); acc.y = fmaf(hv.y, w1.y, acc.y);
        acc.z = fmaf(hv.y, w1.z, acc.z); acc.w = fmaf(hv.y, w1.w, acc.w);
        float4 w2 = Wv[(k + 2) * Kout4 + c4];
        acc.x = fmaf(hv.z, w2.x, acc.x); acc.y = fmaf(hv.z, w2.y, acc.y);
        acc.z = fmaf(hv.z, w2.z, acc.z); acc.w = fmaf(hv.z, w2.w, acc.w);
        float4 w3 = Wv[(k + 3) * Kout4 + c4];
        acc.x = fmaf(hv.w, w3.x, acc.x); acc.y = fmaf(hv.w, w3.y, acc.y);
        acc.z = fmaf(hv.w, w3.z, acc.z); acc.w = fmaf(hv.w, w3.w, acc.w);
    }
    ((float4*)t)[item] = acc;
}

// ---------------------------------------------------------------- out = b + t * dinv^2 (self-loop term)
__global__ void k_init_out(const float* __restrict__ t, const float* __restrict__ dinv,
                           const float* __restrict__ b, float* __restrict__ out,
                           int n, int Kout4) {
    int idx = blockIdx.x * blockDim.x + threadIdx.x;
    int total = n * Kout4;
    if (idx >= total) return;
    int row = idx / Kout4;
    int c4  = idx - row * Kout4;
    float d = dinv[row]; float d2 = d * d;
    float4 tv = ((const float4*)t)[idx];
    float4 bv = ((const float4*)b)[c4];
    float4 o;
    o.x = bv.x + tv.x * d2; o.y = bv.y + tv.y * d2;
    o.z = bv.z + tv.z * d2; o.w = bv.w + tv.w * d2;
    ((float4*)out)[idx] = o;
}

// ---------------------------------------------------------------- edge scatter: out[dst] += t[src]*norm
__device__ __forceinline__ void red_add_v4(float* p, float4 v) {
    asm volatile("red.global.add.v4.f32 [%0], {%1, %2, %3, %4};"
                 :: "l"(p), "f"(v.x), "f"(v.y), "f"(v.z), "f"(v.w) : "memory");
}
__global__ void k_scatter(const int* __restrict__ src, const int* __restrict__ dst,
                          const float* __restrict__ dinv,
                          const float* __restrict__ t, float* __restrict__ out,
                          int E, int Kout4) {
    int e = blockIdx.x * blockDim.x + threadIdx.x;
    if (e >= E) return;
    int s = src[e], d = dst[e];
    float norm = dinv[s] * dinv[d];
    const float4* ts = (const float4*)t + s * Kout4;
    float*        od = out + d * (Kout4 * 4);
    #pragma unroll 2
    for (int c4 = 0; c4 < Kout4; c4++) {
        float4 v = ts[c4];
        v.x *= norm; v.y *= norm; v.z *= norm; v.w *= norm;
        red_add_v4(od + c4 * 4, v);
    }
}

// ---------------------------------------------------------------- pooling
__global__ void k_pool_init(float* pool, int total) {
    int i = blockIdx.x * blockDim.x + threadIdx.x;
    if (i < total) pool[i] = 0.0f;   // relu output >= 0, so 0 is the identity for segment max
}
__global__ void k_pool(const float* __restrict__ h, const int* __restrict__ batch,
                       float* __restrict__ pool, int n) {
    int idx = blockIdx.x * blockDim.x + threadIdx.x;
    int total = n * FDIM;
    if (idx >= total) return;
    int node = idx / FDIM;
    int j    = idx - node * FDIM;
    float v = fmaxf(h[idx], 0.0f);
    // nonnegative floats: IEEE order == int order
    atomicMax((int*)&pool[batch[node] * FDIM + j], __float_as_int(v));
}

// ---------------------------------------------------------------- final heads
__global__ void k_final(const float* __restrict__ pool, const float* __restrict__ feat,
                        const float* __restrict__ Wg,  const float* __restrict__ bg,
                        const float* __restrict__ Wf1, const float* __restrict__ bf1,
                        const float* __restrict__ Wf2, const float* __restrict__ bf2,
                        float* __restrict__ out) {
    int g = blockIdx.x;
    int j = threadIdx.x;          // 128 threads
    const float* f = feat + g * FEATD;
    float acc = bf1[j];
    #pragma unroll 4
    for (int k = 0; k < FEATD; k++)
        acc = fmaf(f[k], Wf1[k * 128 + j], acc);
    float contrib = fmaxf(acc, 0.0f) * Wf2[j];
    __shared__ float s[128];
    s[j] = contrib;
    __syncthreads();
    for (int off = 64; off > 0; off >>= 1) {
        if (j < off) s[j] += s[j + off];
        __syncthreads();
    }
    if (j == 0) {
        float x2 = s[0] + bf2[0];
        float a = bg[0];
        #pragma unroll
        for (int k = 0; k < FDIM; k++)
            a = fmaf(pool[g * FDIM + k], Wg[k], a);
        out[g] = fmaxf(a, 0.0f) + x2;
    }
}

// ----------------------------------------------------------------
extern "C" void kernel_launch(void* const* d_in, const int* in_sizes, int n_in,
                              void* d_out, int out_size) {
    const float* x       = (const float*)d_in[0];
    const int*   ei      = (const int*)  d_in[1];
    const int*   batch   = (const int*)  d_in[2];
    const float* feature = (const float*)d_in[3];
    const float* W1 = (const float*)d_in[4];  const float* b1 = (const float*)d_in[5];
    const float* W2 = (const float*)d_in[6];  const float* b2 = (const float*)d_in[7];
    const float* W3 = (const float*)d_in[8];  const float* b3 = (const float*)d_in[9];
    const float* Wg = (const float*)d_in[10]; const float* bg = (const float*)d_in[11];
    const float* Wf1= (const float*)d_in[12]; const float* bf1= (const float*)d_in[13];
    const float* Wf2= (const float*)d_in[14]; const float* bf2= (const float*)d_in[15];

    const int N = in_sizes[2];          // batch vector length == #nodes
    const int E = in_sizes[1] / 2;
    const int G = in_sizes[3] / FEATD;

    float *A, *B, *dinv, *pool;
    cudaGetSymbolAddress((void**)&A,    g_bufA);
    cudaGetSymbolAddress((void**)&B,    g_bufB);
    cudaGetSymbolAddress((void**)&dinv, g_dinv);
    cudaGetSymbolAddress((void**)&pool, g_pool);

    const int* src = ei;
    const int* dst = ei + E;
    float* out = (float*)d_out;

    const int T = 256;
    auto blocks = [&](int work) { return (work + T - 1) / T; };

    // norm
    k_set_deg  <<<blocks(N), T>>>(dinv, N);
    k_count_deg<<<blocks(E), T>>>(dst, dinv, E);
    k_dinv     <<<blocks(N), T>>>(dinv, N);

    // layer 1: x(44) -> 44
    {
        int K4 = FDIM / 4;
        k_mm      <<<blocks(N * K4), T>>>(x, W1, A, N, FDIM, K4, 0);
        k_init_out<<<blocks(N * K4), T>>>(A, dinv, b1, B, N, K4);
        k_scatter <<<blocks(E), T>>>(src, dst, dinv, A, B, E, K4);
    }
    // layer 2: relu(B)(44) -> 88
    {
        int K4 = F2DIM / 4;
        k_mm      <<<blocks(N * K4), T>>>(B, W2, A, N, FDIM, K4, 1);
        k_init_out<<<blocks(N * K4), T>>>(A, dinv, b2, B, N, K4);
        k_scatter <<<blocks(E), T>>>(src, dst, dinv, A, B, E, K4);
    }
    // layer 3: relu(B)(88) -> 44
    {
        int K4 = FDIM / 4;
        k_mm      <<<blocks(N * K4), T>>>(B, W3, A, N, F2DIM, K4, 1);
        k_init_out<<<blocks(N * K4), T>>>(A, dinv, b3, B, N, K4);
        k_scatter <<<blocks(E), T>>>(src, dst, dinv, A, B, E, K4);
    }

    // pool (segment max over relu(B))
    k_pool_init<<<blocks(G * FDIM), T>>>(pool, G * FDIM);
    k_pool     <<<blocks(N * FDIM), T>>>(B, batch, pool, N);

    // heads
    k_final<<<G, 128>>>(pool, feature, Wg, bg, Wf1, bf1, Wf2, bf2, out);
}